// round 16
// baseline (speedup 1.0000x reference)
#include <cuda_runtime.h>
#include <cstdint>

#define CB 8
#define CN 2048
#define CD 256
#define CH 4
#define CHD 64
#define CM (CB*CN)      // 16384 rows
#define NKT (CN/64)     // 32 key tiles per (b,h)

// Q scale: 1/sqrt(64) * log2(e)  (softmax runs in exp2 domain)
#define QSCALE 0.1803368801111204f

// Scratch (allocation-free rule: __device__ globals). All tf32 bit buffers.
__device__ uint32_t g_xt [CM*CD];     // x, A-frag packed
__device__ uint32_t g_wq [CD*CD];     // weights, B-frag packed
__device__ uint32_t g_wk [CD*CD];
__device__ uint32_t g_wv [CD*CD];
__device__ uint32_t g_wo [CD*CD];
__device__ uint32_t g_wu [2*CD*CD];
__device__ uint32_t g_Qp [CM*CD];     // Q packed in attn A-frag order (scaled)
__device__ uint32_t g_Kp [CM*CD];     // K packed in S-mma B-frag order
__device__ uint32_t g_Vp [CM*CD];     // V packed in PV-mma B-frag order
__device__ uint32_t g_CTX[CM*CD];     // attention out, A-frag packed
__device__ uint32_t g_MSG[CM*CD];     // messages, A-frag packed

// ---------------------------------------------------------------------------
// helpers
// ---------------------------------------------------------------------------
__device__ __forceinline__ uint32_t f2tf32(float f) {
    uint32_t u;
    asm("cvt.rna.tf32.f32 %0, %1;" : "=r"(u) : "f"(f));
    return u;
}

__device__ __forceinline__ float fexp2(float x) {
    float y;
    asm("ex2.approx.f32 %0, %1;" : "=f"(y) : "f"(x));
    return y;
}

__device__ __forceinline__ void mma_tf32(float c[4],
                                         uint32_t a0, uint32_t a1, uint32_t a2, uint32_t a3,
                                         uint32_t b0, uint32_t b1)
{
    asm volatile(
        "mma.sync.aligned.m16n8k8.row.col.f32.tf32.tf32.f32 "
        "{%0,%1,%2,%3}, {%4,%5,%6,%7}, {%8,%9}, {%0,%1,%2,%3};\n"
        : "+f"(c[0]), "+f"(c[1]), "+f"(c[2]), "+f"(c[3])
        : "r"(a0), "r"(a1), "r"(a2), "r"(a3), "r"(b0), "r"(b1));
}

__device__ __forceinline__ void cp16(uint32_t smem_addr, const void* gptr) {
    asm volatile("cp.async.cg.shared.global [%0], [%1], 16;"
                 :: "r"(smem_addr), "l"(gptr));
}

// ---- GEMM operand pack layouts --------------------------------------------
__device__ __forceinline__ size_t a_pack_idx(int m, int k, int ka32) {
    int lane = (m & 7)*4 + (k & 3);
    int slot = ((m >> 3) & 1) + 2*((k >> 2) & 1);
    return ((((size_t)(m >> 4)*ka32 + (k >> 5))*4 + ((k >> 3) & 3))*128)
           + lane*4 + slot;
}
__device__ __forceinline__ size_t b_pack_idx(int k, int n, int kt32) {
    int q = (n >> 5) & 3, ni = (n >> 3) & 3, g = n & 7;
    int lane = g*4 + (k & 3);
    int slot = ((k >> 2) & 1) + 2*(ni & 1);
    return (((size_t)(n >> 7)*kt32 + (k >> 5))*4096)
           + (((q*4 + ((k >> 3) & 3))*2 + (ni >> 1))*128) + lane*4 + slot;
}

// ---- attention packed-layout index helpers --------------------------------
__device__ __forceinline__ size_t k_pack_idx(int m, int col) {
    int b = m >> 11, key = m & 2047;
    int kt = key >> 6, kp = key & 63;
    int h = col >> 6, d = col & 63;
    int g = kp & 7, jb = kp >> 3;
    int kc = d >> 3, dt = d & 7, t = dt & 3;
    int slot = ((jb & 1) << 1) | (dt >> 2);
    int lane = (g << 2) | t;
    size_t tile = (size_t)(b*CH + h) * NKT + kt;
    return tile*4096 + (size_t)((((kc<<2) | (jb>>1))<<7) + (lane<<2) + slot);
}
__device__ __forceinline__ size_t v_pack_idx(int m, int col) {
    int b = m >> 11, key = m & 2047;
    int kt = key >> 6, kp = key & 63;
    int h = col >> 6, d = col & 63;
    int g = d & 7, jb = d >> 3;
    int kc = kp >> 3, kt8 = kp & 7, t = kt8 & 3;
    int slot = ((jb & 1) << 1) | (kt8 >> 2);
    int lane = (g << 2) | t;
    size_t tile = (size_t)(b*CH + h) * NKT + kt;
    return tile*4096 + (size_t)((((kc<<2) | (jb>>1))<<7) + (lane<<2) + slot);
}
__device__ __forceinline__ size_t q_pack_idx(int m, int col) {
    int tile16 = m >> 4, rr = m & 15;
    int g = rr & 7, half = rr >> 3;
    int h = col >> 6, d = col & 63;
    int kc = d >> 3, dt = d & 7, t = dt & 3;
    int slot = half | ((dt >> 2) << 1);
    int lane = (g << 2) | t;
    return (((size_t)tile16*CH + h)*8 + kc)*128 + (lane<<2) + slot;
}

// ---------------------------------------------------------------------------
// cvt kernel: fp32 -> tf32 bits, packed into GEMM fragment layouts
// ---------------------------------------------------------------------------
__global__ void cvt_kernel(const float* __restrict__ x,  const float* __restrict__ Wq,
                           const float* __restrict__ Wk, const float* __restrict__ Wv,
                           const float* __restrict__ Wo, const float* __restrict__ Wu,
                           uint32_t* xt, uint32_t* wq, uint32_t* wk,
                           uint32_t* wv, uint32_t* wo, uint32_t* wu)
{
    int i = blockIdx.x * 256 + threadIdx.x;
    if (i < CM*CD) { xt[a_pack_idx(i >> 8, i & 255, 8)] = f2tf32(x[i]); return; }
    i -= CM*CD;
    if (i < CD*CD) { wq[b_pack_idx(i >> 8, i & 255, 8)] = f2tf32(Wq[i]); return; }
    i -= CD*CD;
    if (i < CD*CD) { wk[b_pack_idx(i >> 8, i & 255, 8)] = f2tf32(Wk[i]); return; }
    i -= CD*CD;
    if (i < CD*CD) { wv[b_pack_idx(i >> 8, i & 255, 8)] = f2tf32(Wv[i]); return; }
    i -= CD*CD;
    if (i < CD*CD) { wo[b_pack_idx(i >> 8, i & 255, 8)] = f2tf32(Wo[i]); return; }
    i -= CD*CD;
    wu[b_pack_idx(i >> 8, i & 255, 16)] = f2tf32(Wu[i]);
}
#define CVT_TOTAL (CM*CD + 4*CD*CD + 2*CD*CD)

// ---------------------------------------------------------------------------
// tf32 GEMM, frag-packed operands, cp.async double-buffered.
// CTA tile 64x128 (was 128x128), warp tile 32x32, 8 warps (2x4),
// __launch_bounds__(256,3): ~70 regs -> 3 CTAs/SM = 24 warps (occupancy fix).
// mode: 0 = fp32 out + ReLU; 1 = A-frag-packed tf32 (MSG);
//       2 = packed K; 3 = packed V; 4 = packed Q (xQSCALE).
// ---------------------------------------------------------------------------
#define GA_U32 2048                          // 64 rows x 32 k
#define GB_U32 4096                          // 32 k x 128 n
#define GSMEM ((2*(GA_U32 + GB_U32))*4)      // 49,152 B

__global__ __launch_bounds__(256, 3)
void gemm_tt_kernel(const uint32_t* __restrict__ A, const uint32_t* __restrict__ A2,
                    const uint32_t* __restrict__ W, const float* __restrict__ bias,
                    void* __restrict__ Cout, int K1, int Ktot, int mode)
{
    extern __shared__ uint32_t gsm[];
    const uint32_t sbase = (uint32_t)__cvta_generic_to_shared(gsm);

    const int tid  = threadIdx.x;
    const int lane = tid & 31;
    const int w    = tid >> 5;
    const int g    = lane >> 2;
    const int t    = lane & 3;
    const int m0 = blockIdx.x * 64;
    const int n0 = blockIdx.y * 128;
    const int tile0 = m0 >> 4;               // 4 consecutive tile16 blocks
    const int wm2 = (w >> 2) * 2;            // warp's first tile16 (local 0..3)
    const int q   = w & 3;                   // warp's n-quadrant

    float acc[2][4][4];
    #pragma unroll
    for (int mi = 0; mi < 2; mi++)
        #pragma unroll
        for (int ni = 0; ni < 4; ni++)
            #pragma unroll
            for (int e = 0; e < 4; e++) acc[mi][ni][e] = 0.f;

    auto stage = [&](int c, int d) {
        int k0 = c * 32;
        const uint32_t* src; int cc, ka32;
        if (k0 < K1) { src = A;  cc = c;             ka32 = K1 >> 5;          }
        else         { src = A2; cc = c - (K1 >> 5); ka32 = (Ktot - K1) >> 5; }
        uint32_t abase = sbase + (uint32_t)d * (GA_U32*4);
        uint32_t bbase = sbase + (2*GA_U32 + (uint32_t)d * GB_U32) * 4;
        #pragma unroll
        for (int u = 0; u < 2; u++) {
            int idx = tid + 256*u;           // 512 cp cover 2048 u32
            int j = idx >> 7;                // block 0..3
            int within = (idx & 127) * 4;
            cp16(abase + idx*16, src + ((size_t)(tile0 + j)*ka32 + cc)*512 + within);
        }
        const uint32_t* wsrc = W + ((size_t)(n0 >> 7)*(Ktot >> 5) + c)*4096;
        #pragma unroll
        for (int u = 0; u < 4; u++) {
            int idx = tid + 256*u;           // 1024 cp cover 4096 u32
            cp16(bbase + idx*16, wsrc + idx*4);
        }
        asm volatile("cp.async.commit_group;");
    };

    const int nc = Ktot / 32;
    stage(0, 0);

    for (int c = 0; c < nc; c++) {
        asm volatile("cp.async.wait_group 0;");
        __syncthreads();
        if (c + 1 < nc) stage(c + 1, (c + 1) & 1);

        const uint32_t* As = gsm + (c & 1) * GA_U32;
        const uint32_t* Bs = gsm + 2*GA_U32 + (c & 1) * GB_U32;

        #pragma unroll
        for (int kcl = 0; kcl < 4; kcl++) {
            uint4 af[2];
            #pragma unroll
            for (int mi = 0; mi < 2; mi++)
                af[mi] = *(const uint4*)(As + (wm2 + mi)*512 + kcl*128 + lane*4);
            uint4 b01 = *(const uint4*)(Bs + ((q*4 + kcl)*2    )*128 + lane*4);
            uint4 b23 = *(const uint4*)(Bs + ((q*4 + kcl)*2 + 1)*128 + lane*4);
            #pragma unroll
            for (int mi = 0; mi < 2; mi++) {
                mma_tf32(acc[mi][0], af[mi].x, af[mi].y, af[mi].z, af[mi].w, b01.x, b01.y);
                mma_tf32(acc[mi][1], af[mi].x, af[mi].y, af[mi].z, af[mi].w, b01.z, b01.w);
                mma_tf32(acc[mi][2], af[mi].x, af[mi].y, af[mi].z, af[mi].w, b23.x, b23.y);
                mma_tf32(acc[mi][3], af[mi].x, af[mi].y, af[mi].z, af[mi].w, b23.z, b23.w);
            }
        }
    }

    const int warpM = (w >> 2) * 32;
    const int warpN = q * 32;
    #pragma unroll
    for (int ni = 0; ni < 4; ni++) {
        int col0 = n0 + warpN + ni*8 + t*2;
        int col1 = col0 + 1;
        float bx = bias[col0], by = bias[col1];
        #pragma unroll
        for (int mi = 0; mi < 2; mi++) {
            int row0 = m0 + warpM + mi*16 + g;
            int row1 = row0 + 8;
            float e0 = acc[mi][ni][0] + bx;
            float e1 = acc[mi][ni][1] + by;
            float e2 = acc[mi][ni][2] + bx;
            float e3 = acc[mi][ni][3] + by;
            if (mode == 0) {
                float* C = (float*)Cout;
                *(float2*)(C + (size_t)row0*CD + col0) =
                    make_float2(fmaxf(e0, 0.f), fmaxf(e1, 0.f));
                *(float2*)(C + (size_t)row1*CD + col0) =
                    make_float2(fmaxf(e2, 0.f), fmaxf(e3, 0.f));
            } else if (mode == 1) {
                uint32_t* C = (uint32_t*)Cout;
                C[a_pack_idx(row0, col0, 8)] = f2tf32(e0);
                C[a_pack_idx(row0, col1, 8)] = f2tf32(e1);
                C[a_pack_idx(row1, col0, 8)] = f2tf32(e2);
                C[a_pack_idx(row1, col1, 8)] = f2tf32(e3);
            } else if (mode == 2) {
                uint32_t* C = (uint32_t*)Cout;
                C[k_pack_idx(row0, col0)] = f2tf32(e0);
                C[k_pack_idx(row0, col1)] = f2tf32(e1);
                C[k_pack_idx(row1, col0)] = f2tf32(e2);
                C[k_pack_idx(row1, col1)] = f2tf32(e3);
            } else if (mode == 3) {
                uint32_t* C = (uint32_t*)Cout;
                C[v_pack_idx(row0, col0)] = f2tf32(e0);
                C[v_pack_idx(row0, col1)] = f2tf32(e1);
                C[v_pack_idx(row1, col0)] = f2tf32(e2);
                C[v_pack_idx(row1, col1)] = f2tf32(e3);
            } else {
                uint32_t* C = (uint32_t*)Cout;
                C[q_pack_idx(row0, col0)] = f2tf32(e0 * QSCALE);
                C[q_pack_idx(row0, col1)] = f2tf32(e1 * QSCALE);
                C[q_pack_idx(row1, col0)] = f2tf32(e2 * QSCALE);
                C[q_pack_idx(row1, col1)] = f2tf32(e3 * QSCALE);
            }
        }
    }
}

// ---------------------------------------------------------------------------
// Flash attention (causal), tf32 MMA. 32 Q-rows/warp, 128-thread CTAs,
// 2 CTAs/SM, paired 128-row Q tiles. Merged 64-key softmax in exp2 domain.
// (unchanged from round 15)
// ---------------------------------------------------------------------------
#define TILE_U32 4096
#define ABUF_U32 (2*TILE_U32)                 // K tile + V tile
#define SMEM_ATTN (2*ABUF_U32*4)              // 65,536 B per CTA

__global__ __launch_bounds__(128, 2)
void attn_mma_kernel(const uint32_t* __restrict__ Qp, const uint32_t* __restrict__ Kp,
                     const uint32_t* __restrict__ Vp, uint32_t* __restrict__ CTX)
{
    extern __shared__ uint32_t sm_u[];
    const uint32_t sbase = (uint32_t)__cvta_generic_to_shared(sm_u);

    const int tid  = threadIdx.x;
    const int lane = tid & 31;
    const int w    = tid >> 5;                  // 0..3
    const int g    = lane >> 2;
    const int t    = lane & 3;

    const int px = blockIdx.x;                  // 0..7
    const int h = blockIdx.y, b = blockIdx.z;
    const size_t tile0 = (size_t)(b*CH + h) * NKT;

    auto stage = [&](int kt, int d) {
        const uint32_t* gK = Kp + (tile0 + kt) * TILE_U32;
        const uint32_t* gV = Vp + (tile0 + kt) * TILE_U32;
        uint32_t ks = sbase + (uint32_t)d * (ABUF_U32*4);
        uint32_t vs = ks + TILE_U32*4;
        #pragma unroll
        for (int p = 0; p < 8; p++) {
            int idx = tid + 128*p;
            cp16(ks + idx*16, gK + idx*4);
            cp16(vs + idx*16, gV + idx*4);
        }
        asm volatile("cp.async.commit_group;");
    };

    #pragma unroll 1
    for (int pass = 0; pass < 2; pass++) {
        const int qb = pass ? 15 - px : px;     // 128-row Q tiles, 16 per (b,h)
        const int q0 = qb * 128;
        const int warpRow = q0 + w*32;

        uint4 qa[2][8];
        #pragma unroll
        for (int mi = 0; mi < 2; mi++) {
            const uint32_t* qbase =
                Qp + ((((size_t)b*(CN/16) + (q0>>4) + 2*w + mi)*CH + h) * 8) * 128 + lane*4;
            #pragma unroll
            for (int kc = 0; kc < 8; kc++)
                qa[mi][kc] = *(const uint4*)(qbase + kc*128);
        }

        float of[2][8][4];
        #pragma unroll
        for (int mi = 0; mi < 2; mi++)
            #pragma unroll
            for (int j = 0; j < 8; j++)
                #pragma unroll
                for (int e = 0; e < 4; e++) of[mi][j][e] = 0.f;
        float mA[2] = {-1e30f, -1e30f}, mB[2] = {-1e30f, -1e30f};
        float lA[2] = {0.f, 0.f},       lB[2] = {0.f, 0.f};

        const int nkt = 2*qb + 2;

        __syncthreads();          // pass boundary: prior readers of smem done
        stage(0, 0);

        for (int kt = 0; kt < nkt; kt++) {
            asm volatile("cp.async.wait_group 0;");
            __syncthreads();
            if (kt + 1 < nkt) stage(kt + 1, (kt + 1) & 1);

            if (kt*64 > warpRow + 31) continue;   // warp fully above diagonal

            const uint32_t* Ks = sm_u + (kt & 1) * ABUF_U32;
            const uint32_t* Vs = Ks + TILE_U32;

            // ---- S = Q K^T over the full 64-key tile ----
            float sc[2][8][4];
            #pragma unroll
            for (int mi = 0; mi < 2; mi++)
                #pragma unroll
                for (int j = 0; j < 8; j++)
                    #pragma unroll
                    for (int e = 0; e < 4; e++) sc[mi][j][e] = 0.f;

            #pragma unroll
            for (int kc = 0; kc < 8; kc++) {
                uint4 kf[4];
                #pragma unroll
                for (int jp = 0; jp < 4; jp++)
                    kf[jp] = *(const uint4*)(Ks + (kc*4 + jp)*128 + lane*4);
                #pragma unroll
                for (int mi = 0; mi < 2; mi++) {
                    #pragma unroll
                    for (int jp = 0; jp < 4; jp++) {
                        mma_tf32(sc[mi][2*jp    ], qa[mi][kc].x, qa[mi][kc].y,
                                 qa[mi][kc].z, qa[mi][kc].w, kf[jp].x, kf[jp].y);
                        mma_tf32(sc[mi][2*jp + 1], qa[mi][kc].x, qa[mi][kc].y,
                                 qa[mi][kc].z, qa[mi][kc].w, kf[jp].z, kf[jp].w);
                    }
                }
            }

            // ---- causal mask (diagonal-overlapping tiles only) ----
            if (kt*64 + 63 > warpRow) {
                #pragma unroll
                for (int mi = 0; mi < 2; mi++) {
                    int rA = warpRow + mi*16 + g;
                    int rB = rA + 8;
                    #pragma unroll
                    for (int j = 0; j < 8; j++) {
                        int c0 = kt*64 + j*8 + t*2;
                        int c1 = c0 + 1;
                        if (c0 > rA) sc[mi][j][0] = -1e30f;
                        if (c1 > rA) sc[mi][j][1] = -1e30f;
                        if (c0 > rB) sc[mi][j][2] = -1e30f;
                        if (c1 > rB) sc[mi][j][3] = -1e30f;
                    }
                }
            }

            // ---- single online-softmax update over all 64 keys (exp2) ----
            #pragma unroll
            for (int mi = 0; mi < 2; mi++) {
                float mxA = -1e30f, mxB = -1e30f;
                #pragma unroll
                for (int j = 0; j < 8; j++) {
                    mxA = fmaxf(mxA, fmaxf(sc[mi][j][0], sc[mi][j][1]));
                    mxB = fmaxf(mxB, fmaxf(sc[mi][j][2], sc[mi][j][3]));
                }
                mxA = fmaxf(mxA, __shfl_xor_sync(0xffffffffu, mxA, 1));
                mxA = fmaxf(mxA, __shfl_xor_sync(0xffffffffu, mxA, 2));
                mxB = fmaxf(mxB, __shfl_xor_sync(0xffffffffu, mxB, 1));
                mxB = fmaxf(mxB, __shfl_xor_sync(0xffffffffu, mxB, 2));

                float nmA = fmaxf(mA[mi], mxA), nmB = fmaxf(mB[mi], mxB);
                float alA = fexp2(mA[mi] - nmA), alB = fexp2(mB[mi] - nmB);
                mA[mi] = nmA; mB[mi] = nmB;

                float sumA = 0.f, sumB = 0.f;
                #pragma unroll
                for (int j = 0; j < 8; j++) {
                    sc[mi][j][0] = fexp2(sc[mi][j][0] - nmA);
                    sc[mi][j][1] = fexp2(sc[mi][j][1] - nmA);
                    sc[mi][j][2] = fexp2(sc[mi][j][2] - nmB);
                    sc[mi][j][3] = fexp2(sc[mi][j][3] - nmB);
                    sumA += sc[mi][j][0] + sc[mi][j][1];
                    sumB += sc[mi][j][2] + sc[mi][j][3];
                }
                sumA += __shfl_xor_sync(0xffffffffu, sumA, 1);
                sumA += __shfl_xor_sync(0xffffffffu, sumA, 2);
                sumB += __shfl_xor_sync(0xffffffffu, sumB, 1);
                sumB += __shfl_xor_sync(0xffffffffu, sumB, 2);
                lA[mi] = lA[mi] * alA + sumA;
                lB[mi] = lB[mi] * alB + sumB;

                #pragma unroll
                for (int j = 0; j < 8; j++) {
                    of[mi][j][0] *= alA; of[mi][j][1] *= alA;
                    of[mi][j][2] *= alB; of[mi][j][3] *= alB;
                }
            }

            // ---- O += P V; P frags via shuffle, V frags shared by mi ----
            const int srcA = (lane & ~3) | (t >> 1);
            const int srcB = srcA + 2;
            const bool odd = (t & 1);
            #pragma unroll
            for (int kcl = 0; kcl < 8; kcl++) {
                uint32_t a[2][4];
                #pragma unroll
                for (int mi = 0; mi < 2; mi++) {
                    float x0 = __shfl_sync(0xffffffffu, sc[mi][kcl][0], srcA);
                    float x1 = __shfl_sync(0xffffffffu, sc[mi][kcl][1], srcA);
                    float y0 = __shfl_sync(0xffffffffu, sc[mi][kcl][0], srcB);
                    float y1 = __shfl_sync(0xffffffffu, sc[mi][kcl][1], srcB);
                    float z0 = __shfl_sync(0xffffffffu, sc[mi][kcl][2], srcA);
                    float z1 = __shfl_sync(0xffffffffu, sc[mi][kcl][3], srcA);
                    float w0 = __shfl_sync(0xffffffffu, sc[mi][kcl][2], srcB);
                    float w1 = __shfl_sync(0xffffffffu, sc[mi][kcl][3], srcB);
                    a[mi][0] = f2tf32(odd ? x1 : x0);
                    a[mi][2] = f2tf32(odd ? y1 : y0);
                    a[mi][1] = f2tf32(odd ? z1 : z0);
                    a[mi][3] = f2tf32(odd ? w1 : w0);
                }
                #pragma unroll
                for (int jp = 0; jp < 4; jp++) {
                    uint4 vf = *(const uint4*)(Vs + (kcl*4 + jp)*128 + lane*4);
                    mma_tf32(of[0][2*jp    ], a[0][0], a[0][1], a[0][2], a[0][3], vf.x, vf.y);
                    mma_tf32(of[0][2*jp + 1], a[0][0], a[0][1], a[0][2], a[0][3], vf.z, vf.w);
                    mma_tf32(of[1][2*jp    ], a[1][0], a[1][1], a[1][2], a[1][3], vf.x, vf.y);
                    mma_tf32(of[1][2*jp + 1], a[1][0], a[1][1], a[1][2], a[1][3], vf.z, vf.w);
                }
            }
        }

        // ---- epilogue: normalize, write CTX A-frag packed ----
        #pragma unroll
        for (int mi = 0; mi < 2; mi++) {
            int rA = (b << 11) + warpRow + mi*16 + g;   // global row
            int rB = rA + 8;
            float invA = 1.f / lA[mi], invB = 1.f / lB[mi];
            #pragma unroll
            for (int j = 0; j < 8; j++) {
                int col0 = (h << 6) + j*8 + t*2;
                int col1 = col0 + 1;
                CTX[a_pack_idx(rA, col0, 8)] = f2tf32(of[mi][j][0]*invA);
                CTX[a_pack_idx(rA, col1, 8)] = f2tf32(of[mi][j][1]*invA);
                CTX[a_pack_idx(rB, col0, 8)] = f2tf32(of[mi][j][2]*invB);
                CTX[a_pack_idx(rB, col1, 8)] = f2tf32(of[mi][j][3]*invB);
            }
        }
    }
}

// ---------------------------------------------------------------------------
extern "C" void kernel_launch(void* const* d_in, const int* in_sizes, int n_in,
                              void* d_out, int out_size)
{
    const float* x  = (const float*)d_in[0];
    // d_in[1] = causal_mask: unused (tril by construction; handled analytically)
    const float* Wq = (const float*)d_in[2];
    const float* bq = (const float*)d_in[3];
    const float* Wk = (const float*)d_in[4];
    const float* bk = (const float*)d_in[5];
    const float* Wv = (const float*)d_in[6];
    const float* bv = (const float*)d_in[7];
    const float* Wo = (const float*)d_in[8];
    const float* bo = (const float*)d_in[9];
    const float* Wu = (const float*)d_in[10];
    const float* bu = (const float*)d_in[11];
    float* out = (float*)d_out;

    uint32_t *xt, *wq, *wk, *wv, *wo, *wu, *Qp, *Kpp, *Vpp, *Cb, *Mb;
    cudaGetSymbolAddress((void**)&xt,  g_xt);
    cudaGetSymbolAddress((void**)&wq,  g_wq);
    cudaGetSymbolAddress((void**)&wk,  g_wk);
    cudaGetSymbolAddress((void**)&wv,  g_wv);
    cudaGetSymbolAddress((void**)&wo,  g_wo);
    cudaGetSymbolAddress((void**)&wu,  g_wu);
    cudaGetSymbolAddress((void**)&Qp,  g_Qp);
    cudaGetSymbolAddress((void**)&Kpp, g_Kp);
    cudaGetSymbolAddress((void**)&Vpp, g_Vp);
    cudaGetSymbolAddress((void**)&Cb,  g_CTX);
    cudaGetSymbolAddress((void**)&Mb,  g_MSG);

    cudaFuncSetAttribute(gemm_tt_kernel,
                         cudaFuncAttributeMaxDynamicSharedMemorySize, GSMEM);
    cudaFuncSetAttribute(attn_mma_kernel,
                         cudaFuncAttributeMaxDynamicSharedMemorySize, SMEM_ATTN);

    // 1) convert + pack x and weights
    cvt_kernel<<<CVT_TOTAL/256, 256>>>(x, Wq, Wk, Wv, Wo, Wu, xt, wq, wk, wv, wo, wu);

    dim3 gg(CM/64, CD/128);   // 256 x 2 = 512 CTAs (3/SM capacity)

    // 2) projections (outputs packed for attention)
    gemm_tt_kernel<<<gg, 256, GSMEM>>>(xt, xt, wq, bq, Qp,  256, 256, 4);
    gemm_tt_kernel<<<gg, 256, GSMEM>>>(xt, xt, wk, bk, Kpp, 256, 256, 2);
    gemm_tt_kernel<<<gg, 256, GSMEM>>>(xt, xt, wv, bv, Vpp, 256, 256, 3);

    // 3) causal flash attention (merged 64-key softmax, exp2 domain)
    attn_mma_kernel<<<dim3(CN/256, CH, CB), 128, SMEM_ATTN>>>(Qp, Kpp, Vpp, Cb);

    // 4) output projection + update MLP (concat fused)
    gemm_tt_kernel<<<gg, 256, GSMEM>>>(Cb, Cb, wo, bo, Mb, 256, 256, 1);
    gemm_tt_kernel<<<gg, 256, GSMEM>>>(xt, Mb, wu, bu, out, 256, 512, 0);
}

// round 17
// speedup vs baseline: 1.8569x; 1.8569x over previous
#include <cuda_runtime.h>
#include <cstdint>

#define CB 8
#define CN 2048
#define CD 256
#define CH 4
#define CHD 64
#define CM (CB*CN)      // 16384 rows
#define NKT (CN/64)     // 32 key tiles per (b,h)

// Q scale: 1/sqrt(64) * log2(e)  (softmax runs in exp2 domain)
#define QSCALE 0.1803368801111204f

// Scratch (allocation-free rule: __device__ globals). All fp16x2 bit buffers.
__device__ uint32_t g_xt [CM*CD/2];   // x, A-frag packed (half2)
__device__ uint32_t g_wq [CD*CD/2];   // weights, B-frag packed (half2)
__device__ uint32_t g_wk [CD*CD/2];
__device__ uint32_t g_wv [CD*CD/2];
__device__ uint32_t g_wo [CD*CD/2];
__device__ uint32_t g_wu [CD*CD];     // 2*CD*CD halves
__device__ uint32_t g_Qp [CM*CD/2];   // Q, attn A-frag packed (scaled)
__device__ uint32_t g_Kp [CM*CD/2];   // K, S-mma B-frag packed
__device__ uint32_t g_Vp [CM*CD/2];   // V, PV-mma B-frag packed
__device__ uint32_t g_CTX[CM*CD/2];   // attention out, A-frag packed
__device__ uint32_t g_MSG[CM*CD/2];   // messages, A-frag packed

// ---------------------------------------------------------------------------
// helpers
// ---------------------------------------------------------------------------
__device__ __forceinline__ uint32_t f2h2(float lo, float hi) {
    uint32_t u;
    asm("cvt.rn.f16x2.f32 %0, %1, %2;" : "=r"(u) : "f"(hi), "f"(lo));
    return u;
}

__device__ __forceinline__ float fexp2(float x) {
    float y;
    asm("ex2.approx.f32 %0, %1;" : "=f"(y) : "f"(x));
    return y;
}

// m16n8k16 fp16 mma, fp32 accumulate
__device__ __forceinline__ void mma_f16(float c[4],
                                        uint32_t a0, uint32_t a1, uint32_t a2, uint32_t a3,
                                        uint32_t b0, uint32_t b1)
{
    asm volatile(
        "mma.sync.aligned.m16n8k16.row.col.f32.f16.f16.f32 "
        "{%0,%1,%2,%3}, {%4,%5,%6,%7}, {%8,%9}, {%0,%1,%2,%3};\n"
        : "+f"(c[0]), "+f"(c[1]), "+f"(c[2]), "+f"(c[3])
        : "r"(a0), "r"(a1), "r"(a2), "r"(a3), "r"(b0), "r"(b1));
}

__device__ __forceinline__ void cp16(uint32_t smem_addr, const void* gptr) {
    asm volatile("cp.async.cg.shared.global [%0], [%1], 16;"
                 :: "r"(smem_addr), "l"(gptr));
}

// ---- fp16 fragment pack layouts (u32 = half2 indices) ---------------------
// A-frag (m16n8k16): a0=(row g, k 2t..2t+1), a1=(g+8,..), a2=(g, k+8..), a3=(g+8, k+8..)
// k must be even (pair k, k+1).
__device__ __forceinline__ size_t a_pack16(int m, int k, int ka32) {
    int c = k >> 5, ks = (k >> 4) & 1, kk = k & 15;
    int t = (kk >> 1) & 3, hi = kk >> 3;
    int slot = ((m >> 3) & 1) | (hi << 1);
    int lane = (m & 7)*4 + t;
    return ((((size_t)(m >> 4)*ka32 + c)*2 + ks)*128) + lane*4 + slot;
}
// B-frag: b0=(k 2t..2t+1, n g), b1=(k 2t+8.., n g). k even.
__device__ __forceinline__ size_t b_pack16(int k, int n, int kt32) {
    int c = k >> 5, ks = (k >> 4) & 1, kk = k & 15;
    int t = (kk >> 1) & 3, r = kk >> 3;
    int q = (n >> 5) & 3, ni = (n >> 3) & 3, g = n & 7;
    int u = ni >> 1, e = (ni & 1)*2 + r;
    return ((size_t)(n >> 7)*kt32 + c)*2048 + (((q*2 + ks)*2 + u)*128) + (g*4 + t)*4 + e;
}
// attention K tile (2048 u32): n=key, k=d. col even (pair d,d+1).
__device__ __forceinline__ size_t k_pack16(int m, int col) {
    int b = m >> 11, key = m & 2047;
    int kt = key >> 6, kk = key & 63;
    int jp = kk >> 3, gk = kk & 7;
    int h = col >> 6, d = col & 63;
    int kc = d >> 4, dd = d & 15;
    int t = (dd >> 1) & 3, r = dd >> 3;
    size_t tile = (size_t)(b*CH + h)*NKT + kt;
    return tile*2048 + ((kc*4 + (jp >> 1))*128) + (gk*4 + t)*4 + ((jp & 1)*2 + r);
}
// attention V tile (2048 u32): n=d, k=key. m (key) even (pair key,key+1).
__device__ __forceinline__ size_t v_pack16(int m, int col) {
    int b = m >> 11, key = m & 2047;
    int kt = key >> 6, kk = key & 63;
    int kcl = kk >> 4, kp = (kk & 15) >> 1;
    int t = kp & 3, r = kp >> 2;
    int h = col >> 6, d = col & 63;
    int jp = d >> 3, gd = d & 7;
    size_t tile = (size_t)(b*CH + h)*NKT + kt;
    return tile*2048 + ((kcl*4 + (jp >> 1))*128) + (gd*4 + t)*4 + ((jp & 1)*2 + r);
}
// attention Q A-frag: per (tile16,h): 4 kc x 128. col even.
__device__ __forceinline__ size_t q_pack16(int m, int col) {
    int h = col >> 6, d = col & 63;
    int kc = d >> 4, dd = d & 15;
    int t = (dd >> 1) & 3, hi = dd >> 3;
    int slot = ((m >> 3) & 1) | (hi << 1);
    int lane = (m & 7)*4 + t;
    return (((size_t)(m >> 4)*CH + h)*4 + kc)*128 + lane*4 + slot;
}

// ---------------------------------------------------------------------------
// cvt kernel: fp32 -> packed half2 for x and all weights (pair-indexed)
// ---------------------------------------------------------------------------
#define XP (CM*CD/2)
#define WP (CD*CD/2)
#define CVT_TOTAL (XP + 4*WP + CD*CD)
__global__ void cvt_kernel(const float* __restrict__ x,  const float* __restrict__ Wq,
                           const float* __restrict__ Wk, const float* __restrict__ Wv,
                           const float* __restrict__ Wo, const float* __restrict__ Wu,
                           uint32_t* xt, uint32_t* wq, uint32_t* wk,
                           uint32_t* wv, uint32_t* wo, uint32_t* wu)
{
    int i = blockIdx.x * 256 + threadIdx.x;
    if (i < XP) {
        int row = i >> 7, k = (i & 127) << 1;
        xt[a_pack16(row, k, 8)] = f2h2(x[row*CD + k], x[row*CD + k + 1]);
        return;
    }
    i -= XP;
    if (i < WP) {
        int k = (i >> 8) << 1, n = i & 255;
        wq[b_pack16(k, n, 8)] = f2h2(Wq[k*CD + n], Wq[(k+1)*CD + n]);
        return;
    }
    i -= WP;
    if (i < WP) {
        int k = (i >> 8) << 1, n = i & 255;
        wk[b_pack16(k, n, 8)] = f2h2(Wk[k*CD + n], Wk[(k+1)*CD + n]);
        return;
    }
    i -= WP;
    if (i < WP) {
        int k = (i >> 8) << 1, n = i & 255;
        wv[b_pack16(k, n, 8)] = f2h2(Wv[k*CD + n], Wv[(k+1)*CD + n]);
        return;
    }
    i -= WP;
    if (i < WP) {
        int k = (i >> 8) << 1, n = i & 255;
        wo[b_pack16(k, n, 8)] = f2h2(Wo[k*CD + n], Wo[(k+1)*CD + n]);
        return;
    }
    i -= WP;
    {
        int k = (i >> 8) << 1, n = i & 255;   // k 0..511
        wu[b_pack16(k, n, 16)] = f2h2(Wu[k*CD + n], Wu[(k+1)*CD + n]);
    }
}

// ---------------------------------------------------------------------------
// fp16 GEMM, frag-packed operands, cp.async double-buffered.
// CTA 128x128, BK=32 (2 k16 steps), 8 warps, warp tile 64x32.
// mode: 0 = fp32 out + ReLU; 1 = A-frag-packed (MSG);
//       2 = packed K; 3 = packed V (key-pair via shfl); 4 = packed Q (xQSCALE).
// ---------------------------------------------------------------------------
#define GA16 2048
#define GB16 2048
#define GSMEM ((2*(GA16 + GB16))*4)          // 32,768 B

__global__ __launch_bounds__(256, 2)
void gemm_tt_kernel(const uint32_t* __restrict__ A, const uint32_t* __restrict__ A2,
                    const uint32_t* __restrict__ W, const float* __restrict__ bias,
                    void* __restrict__ Cout, int K1, int Ktot, int mode)
{
    extern __shared__ uint32_t gsm[];
    const uint32_t sbase = (uint32_t)__cvta_generic_to_shared(gsm);

    const int tid  = threadIdx.x;
    const int lane = tid & 31;
    const int w    = tid >> 5;
    const int g    = lane >> 2;
    const int t    = lane & 3;
    const int m0 = blockIdx.x * 128;
    const int n0 = blockIdx.y * 128;
    const int tile0 = m0 >> 4;               // 8 consecutive tile16 blocks
    const int wm4 = (w >> 2) * 4;            // warp's first local tile16
    const int q   = w & 3;                   // warp's n-quadrant

    float acc[4][4][4];
    #pragma unroll
    for (int mi = 0; mi < 4; mi++)
        #pragma unroll
        for (int ni = 0; ni < 4; ni++)
            #pragma unroll
            for (int e = 0; e < 4; e++) acc[mi][ni][e] = 0.f;

    auto stage = [&](int c, int d) {
        int k0 = c * 32;
        const uint32_t* src; int cc, ka32;
        if (k0 < K1) { src = A;  cc = c;             ka32 = K1 >> 5;          }
        else         { src = A2; cc = c - (K1 >> 5); ka32 = (Ktot - K1) >> 5; }
        uint32_t abase = sbase + (uint32_t)d * (GA16*4);
        uint32_t bbase = sbase + (2*GA16 + (uint32_t)d * GB16) * 4;
        #pragma unroll
        for (int u = 0; u < 2; u++) {
            int i = tid + 256*u;             // 512 cp16 cover 2048 u32
            int j = i >> 6;                  // tile16 block 0..7
            int within = (i & 63) * 4;
            cp16(abase + i*16, src + ((size_t)(tile0 + j)*ka32 + cc)*256 + within);
        }
        const uint32_t* wsrc = W + ((size_t)(n0 >> 7)*(Ktot >> 5) + c)*2048;
        #pragma unroll
        for (int u = 0; u < 2; u++) {
            int i = tid + 256*u;
            cp16(bbase + i*16, wsrc + i*4);
        }
        asm volatile("cp.async.commit_group;");
    };

    const int nc = Ktot / 32;
    stage(0, 0);

    for (int c = 0; c < nc; c++) {
        asm volatile("cp.async.wait_group 0;");
        __syncthreads();
        if (c + 1 < nc) stage(c + 1, (c + 1) & 1);

        const uint32_t* As = gsm + (c & 1) * GA16;
        const uint32_t* Bs = gsm + 2*GA16 + (c & 1) * GB16;

        #pragma unroll
        for (int ks = 0; ks < 2; ks++) {
            uint4 af[4];
            #pragma unroll
            for (int mi = 0; mi < 4; mi++)
                af[mi] = *(const uint4*)(As + (wm4 + mi)*256 + ks*128 + lane*4);
            uint4 b01 = *(const uint4*)(Bs + ((q*2 + ks)*2    )*128 + lane*4);
            uint4 b23 = *(const uint4*)(Bs + ((q*2 + ks)*2 + 1)*128 + lane*4);
            #pragma unroll
            for (int mi = 0; mi < 4; mi++) {
                mma_f16(acc[mi][0], af[mi].x, af[mi].y, af[mi].z, af[mi].w, b01.x, b01.y);
                mma_f16(acc[mi][1], af[mi].x, af[mi].y, af[mi].z, af[mi].w, b01.z, b01.w);
                mma_f16(acc[mi][2], af[mi].x, af[mi].y, af[mi].z, af[mi].w, b23.x, b23.y);
                mma_f16(acc[mi][3], af[mi].x, af[mi].y, af[mi].z, af[mi].w, b23.z, b23.w);
            }
        }
    }

    const int warpM = (w >> 2) * 64;
    const int warpN = q * 32;
    #pragma unroll
    for (int ni = 0; ni < 4; ni++) {
        int col0 = n0 + warpN + ni*8 + t*2;
        int col1 = col0 + 1;
        float bx = bias[col0], by = bias[col1];
        #pragma unroll
        for (int mi = 0; mi < 4; mi++) {
            int row0 = m0 + warpM + mi*16 + g;
            int row1 = row0 + 8;
            float e0 = acc[mi][ni][0] + bx;
            float e1 = acc[mi][ni][1] + by;
            float e2 = acc[mi][ni][2] + bx;
            float e3 = acc[mi][ni][3] + by;
            if (mode == 0) {
                float* C = (float*)Cout;
                *(float2*)(C + (size_t)row0*CD + col0) =
                    make_float2(fmaxf(e0, 0.f), fmaxf(e1, 0.f));
                *(float2*)(C + (size_t)row1*CD + col0) =
                    make_float2(fmaxf(e2, 0.f), fmaxf(e3, 0.f));
            } else if (mode == 1) {
                uint32_t* C = (uint32_t*)Cout;
                C[a_pack16(row0, col0, 8)] = f2h2(e0, e1);
                C[a_pack16(row1, col0, 8)] = f2h2(e2, e3);
            } else if (mode == 2) {
                uint32_t* C = (uint32_t*)Cout;
                C[k_pack16(row0, col0)] = f2h2(e0, e1);
                C[k_pack16(row1, col0)] = f2h2(e2, e3);
            } else if (mode == 3) {
                // V: pair across adjacent key rows (g, g^1) via shuffle
                uint32_t* C = (uint32_t*)Cout;
                float p0 = __shfl_xor_sync(0xffffffffu, e0, 4);
                float p1 = __shfl_xor_sync(0xffffffffu, e1, 4);
                float p2 = __shfl_xor_sync(0xffffffffu, e2, 4);
                float p3 = __shfl_xor_sync(0xffffffffu, e3, 4);
                if (!(g & 1)) {
                    C[v_pack16(row0, col0)] = f2h2(e0, p0);
                    C[v_pack16(row0, col1)] = f2h2(e1, p1);
                    C[v_pack16(row1, col0)] = f2h2(e2, p2);
                    C[v_pack16(row1, col1)] = f2h2(e3, p3);
                }
            } else {
                uint32_t* C = (uint32_t*)Cout;
                C[q_pack16(row0, col0)] = f2h2(e0 * QSCALE, e1 * QSCALE);
                C[q_pack16(row1, col0)] = f2h2(e2 * QSCALE, e3 * QSCALE);
            }
        }
    }
}

// ---------------------------------------------------------------------------
// Flash attention (causal), fp16 MMA (m16n8k16). 32 Q-rows/warp, 128-thread
// CTAs, 2/SM, paired 128-row Q tiles, merged 64-key softmax (exp2 domain).
// fp16 k16 removes the P shuffle entirely: P A-frags come straight from sc.
// ---------------------------------------------------------------------------
#define TILE16 2048
#define ABUF16 (2*TILE16)                    // K tile + V tile
#define SMEM_ATTN (2*ABUF16*4)               // 32,768 B per CTA

__global__ __launch_bounds__(128, 2)
void attn_mma_kernel(const uint32_t* __restrict__ Qp, const uint32_t* __restrict__ Kp,
                     const uint32_t* __restrict__ Vp, uint32_t* __restrict__ CTX)
{
    extern __shared__ uint32_t sm_u[];
    const uint32_t sbase = (uint32_t)__cvta_generic_to_shared(sm_u);

    const int tid  = threadIdx.x;
    const int lane = tid & 31;
    const int w    = tid >> 5;                  // 0..3
    const int g    = lane >> 2;
    const int t    = lane & 3;

    const int px = blockIdx.x;                  // 0..7
    const int h = blockIdx.y, b = blockIdx.z;
    const size_t tile0 = (size_t)(b*CH + h) * NKT;

    auto stage = [&](int kt, int d) {
        const uint32_t* gK = Kp + (tile0 + kt) * TILE16;
        const uint32_t* gV = Vp + (tile0 + kt) * TILE16;
        uint32_t ks = sbase + (uint32_t)d * (ABUF16*4);
        uint32_t vs = ks + TILE16*4;
        #pragma unroll
        for (int p = 0; p < 4; p++) {
            int idx = tid + 128*p;              // 512 cp16 per tile
            cp16(ks + idx*16, gK + idx*4);
            cp16(vs + idx*16, gV + idx*4);
        }
        asm volatile("cp.async.commit_group;");
    };

    #pragma unroll 1
    for (int pass = 0; pass < 2; pass++) {
        const int qb = pass ? 15 - px : px;     // 128-row Q tiles, 16 per (b,h)
        const int q0 = qb * 128;
        const int warpRow = q0 + w*32;

        // ---- Q fragments: 8x LDG.128 (4 kc x 2 mi) ----
        uint4 qa[2][4];
        #pragma unroll
        for (int mi = 0; mi < 2; mi++) {
            const uint32_t* qbase =
                Qp + ((((size_t)b*(CN/16) + (q0>>4) + 2*w + mi)*CH + h) * 4) * 128 + lane*4;
            #pragma unroll
            for (int kc = 0; kc < 4; kc++)
                qa[mi][kc] = *(const uint4*)(qbase + kc*128);
        }

        float of[2][8][4];
        #pragma unroll
        for (int mi = 0; mi < 2; mi++)
            #pragma unroll
            for (int j = 0; j < 8; j++)
                #pragma unroll
                for (int e = 0; e < 4; e++) of[mi][j][e] = 0.f;
        float mA[2] = {-1e30f, -1e30f}, mB[2] = {-1e30f, -1e30f};
        float lA[2] = {0.f, 0.f},       lB[2] = {0.f, 0.f};

        const int nkt = 2*qb + 2;

        __syncthreads();          // pass boundary: prior readers of smem done
        stage(0, 0);

        for (int kt = 0; kt < nkt; kt++) {
            asm volatile("cp.async.wait_group 0;");
            __syncthreads();
            if (kt + 1 < nkt) stage(kt + 1, (kt + 1) & 1);

            if (kt*64 > warpRow + 31) continue;   // warp fully above diagonal

            const uint32_t* Ks = sm_u + (kt & 1) * ABUF16;
            const uint32_t* Vs = Ks + TILE16;

            // ---- S = Q K^T over the full 64-key tile ----
            float sc[2][8][4];
            #pragma unroll
            for (int mi = 0; mi < 2; mi++)
                #pragma unroll
                for (int j = 0; j < 8; j++)
                    #pragma unroll
                    for (int e = 0; e < 4; e++) sc[mi][j][e] = 0.f;

            #pragma unroll
            for (int kc = 0; kc < 4; kc++) {
                uint4 kf[4];
                #pragma unroll
                for (int jpu = 0; jpu < 4; jpu++)
                    kf[jpu] = *(const uint4*)(Ks + (kc*4 + jpu)*128 + lane*4);
                #pragma unroll
                for (int mi = 0; mi < 2; mi++) {
                    #pragma unroll
                    for (int jpu = 0; jpu < 4; jpu++) {
                        mma_f16(sc[mi][2*jpu    ], qa[mi][kc].x, qa[mi][kc].y,
                                qa[mi][kc].z, qa[mi][kc].w, kf[jpu].x, kf[jpu].y);
                        mma_f16(sc[mi][2*jpu + 1], qa[mi][kc].x, qa[mi][kc].y,
                                qa[mi][kc].z, qa[mi][kc].w, kf[jpu].z, kf[jpu].w);
                    }
                }
            }

            // ---- causal mask (diagonal-overlapping tiles only) ----
            if (kt*64 + 63 > warpRow) {
                #pragma unroll
                for (int mi = 0; mi < 2; mi++) {
                    int rA = warpRow + mi*16 + g;
                    int rB = rA + 8;
                    #pragma unroll
                    for (int j = 0; j < 8; j++) {
                        int c0 = kt*64 + j*8 + t*2;
                        int c1 = c0 + 1;
                        if (c0 > rA) sc[mi][j][0] = -1e30f;
                        if (c1 > rA) sc[mi][j][1] = -1e30f;
                        if (c0 > rB) sc[mi][j][2] = -1e30f;
                        if (c1 > rB) sc[mi][j][3] = -1e30f;
                    }
                }
            }

            // ---- single online-softmax update over all 64 keys (exp2) ----
            #pragma unroll
            for (int mi = 0; mi < 2; mi++) {
                float mxA = -1e30f, mxB = -1e30f;
                #pragma unroll
                for (int j = 0; j < 8; j++) {
                    mxA = fmaxf(mxA, fmaxf(sc[mi][j][0], sc[mi][j][1]));
                    mxB = fmaxf(mxB, fmaxf(sc[mi][j][2], sc[mi][j][3]));
                }
                mxA = fmaxf(mxA, __shfl_xor_sync(0xffffffffu, mxA, 1));
                mxA = fmaxf(mxA, __shfl_xor_sync(0xffffffffu, mxA, 2));
                mxB = fmaxf(mxB, __shfl_xor_sync(0xffffffffu, mxB, 1));
                mxB = fmaxf(mxB, __shfl_xor_sync(0xffffffffu, mxB, 2));

                float nmA = fmaxf(mA[mi], mxA), nmB = fmaxf(mB[mi], mxB);
                float alA = fexp2(mA[mi] - nmA), alB = fexp2(mB[mi] - nmB);
                mA[mi] = nmA; mB[mi] = nmB;

                float sumA = 0.f, sumB = 0.f;
                #pragma unroll
                for (int j = 0; j < 8; j++) {
                    sc[mi][j][0] = fexp2(sc[mi][j][0] - nmA);
                    sc[mi][j][1] = fexp2(sc[mi][j][1] - nmA);
                    sc[mi][j][2] = fexp2(sc[mi][j][2] - nmB);
                    sc[mi][j][3] = fexp2(sc[mi][j][3] - nmB);
                    sumA += sc[mi][j][0] + sc[mi][j][1];
                    sumB += sc[mi][j][2] + sc[mi][j][3];
                }
                sumA += __shfl_xor_sync(0xffffffffu, sumA, 1);
                sumA += __shfl_xor_sync(0xffffffffu, sumA, 2);
                sumB += __shfl_xor_sync(0xffffffffu, sumB, 1);
                sumB += __shfl_xor_sync(0xffffffffu, sumB, 2);
                lA[mi] = lA[mi] * alA + sumA;
                lB[mi] = lB[mi] * alB + sumB;

                #pragma unroll
                for (int j = 0; j < 8; j++) {
                    of[mi][j][0] *= alA; of[mi][j][1] *= alA;
                    of[mi][j][2] *= alB; of[mi][j][3] *= alB;
                }
            }

            // ---- O += P V; P A-frags packed directly from sc (no shuffle) ----
            #pragma unroll
            for (int kcl = 0; kcl < 4; kcl++) {
                uint32_t a[2][4];
                #pragma unroll
                for (int mi = 0; mi < 2; mi++) {
                    a[mi][0] = f2h2(sc[mi][2*kcl    ][0], sc[mi][2*kcl    ][1]);
                    a[mi][1] = f2h2(sc[mi][2*kcl    ][2], sc[mi][2*kcl    ][3]);
                    a[mi][2] = f2h2(sc[mi][2*kcl + 1][0], sc[mi][2*kcl + 1][1]);
                    a[mi][3] = f2h2(sc[mi][2*kcl + 1][2], sc[mi][2*kcl + 1][3]);
                }
                #pragma unroll
                for (int jpu = 0; jpu < 4; jpu++) {
                    uint4 vf = *(const uint4*)(Vs + (kcl*4 + jpu)*128 + lane*4);
                    mma_f16(of[0][2*jpu    ], a[0][0], a[0][1], a[0][2], a[0][3], vf.x, vf.y);
                    mma_f16(of[0][2*jpu + 1], a[0][0], a[0][1], a[0][2], a[0][3], vf.z, vf.w);
                    mma_f16(of[1][2*jpu    ], a[1][0], a[1][1], a[1][2], a[1][3], vf.x, vf.y);
                    mma_f16(of[1][2*jpu + 1], a[1][0], a[1][1], a[1][2], a[1][3], vf.z, vf.w);
                }
            }
        }

        // ---- epilogue: normalize, write CTX A-frag packed ----
        #pragma unroll
        for (int mi = 0; mi < 2; mi++) {
            int rA = (b << 11) + warpRow + mi*16 + g;   // global row
            int rB = rA + 8;
            float invA = 1.f / lA[mi], invB = 1.f / lB[mi];
            #pragma unroll
            for (int j = 0; j < 8; j++) {
                int col0 = (h << 6) + j*8 + t*2;
                CTX[a_pack16(rA, col0, 8)] = f2h2(of[mi][j][0]*invA, of[mi][j][1]*invA);
                CTX[a_pack16(rB, col0, 8)] = f2h2(of[mi][j][2]*invB, of[mi][j][3]*invB);
            }
        }
    }
}

// ---------------------------------------------------------------------------
extern "C" void kernel_launch(void* const* d_in, const int* in_sizes, int n_in,
                              void* d_out, int out_size)
{
    const float* x  = (const float*)d_in[0];
    // d_in[1] = causal_mask: unused (tril by construction; handled analytically)
    const float* Wq = (const float*)d_in[2];
    const float* bq = (const float*)d_in[3];
    const float* Wk = (const float*)d_in[4];
    const float* bk = (const float*)d_in[5];
    const float* Wv = (const float*)d_in[6];
    const float* bv = (const float*)d_in[7];
    const float* Wo = (const float*)d_in[8];
    const float* bo = (const float*)d_in[9];
    const float* Wu = (const float*)d_in[10];
    const float* bu = (const float*)d_in[11];
    float* out = (float*)d_out;

    uint32_t *xt, *wq, *wk, *wv, *wo, *wu, *Qp, *Kpp, *Vpp, *Cb, *Mb;
    cudaGetSymbolAddress((void**)&xt,  g_xt);
    cudaGetSymbolAddress((void**)&wq,  g_wq);
    cudaGetSymbolAddress((void**)&wk,  g_wk);
    cudaGetSymbolAddress((void**)&wv,  g_wv);
    cudaGetSymbolAddress((void**)&wo,  g_wo);
    cudaGetSymbolAddress((void**)&wu,  g_wu);
    cudaGetSymbolAddress((void**)&Qp,  g_Qp);
    cudaGetSymbolAddress((void**)&Kpp, g_Kp);
    cudaGetSymbolAddress((void**)&Vpp, g_Vp);
    cudaGetSymbolAddress((void**)&Cb,  g_CTX);
    cudaGetSymbolAddress((void**)&Mb,  g_MSG);

    cudaFuncSetAttribute(gemm_tt_kernel,
                         cudaFuncAttributeMaxDynamicSharedMemorySize, GSMEM);
    cudaFuncSetAttribute(attn_mma_kernel,
                         cudaFuncAttributeMaxDynamicSharedMemorySize, SMEM_ATTN);

    // 1) convert + pack x and weights (fp16 fragment layouts)
    cvt_kernel<<<CVT_TOTAL/256, 256>>>(x, Wq, Wk, Wv, Wo, Wu, xt, wq, wk, wv, wo, wu);

    dim3 gg(CM/128, CD/128);   // 128 x 2

    // 2) projections (outputs packed for attention)
    gemm_tt_kernel<<<gg, 256, GSMEM>>>(xt, xt, wq, bq, Qp,  256, 256, 4);
    gemm_tt_kernel<<<gg, 256, GSMEM>>>(xt, xt, wk, bk, Kpp, 256, 256, 2);
    gemm_tt_kernel<<<gg, 256, GSMEM>>>(xt, xt, wv, bv, Vpp, 256, 256, 3);

    // 3) causal flash attention (fp16 mma, merged softmax, exp2 domain)
    attn_mma_kernel<<<dim3(CN/256, CH, CB), 128, SMEM_ATTN>>>(Qp, Kpp, Vpp, Cb);

    // 4) output projection + update MLP (concat fused)
    gemm_tt_kernel<<<gg, 256, GSMEM>>>(Cb, Cb, wo, bo, Mb, 256, 256, 1);
    gemm_tt_kernel<<<gg, 256, GSMEM>>>(xt, Mb, wu, bu, out, 256, 512, 0);
}